// round 13
// baseline (speedup 1.0000x reference)
#include <cuda_runtime.h>
#include <math.h>

#define BS   8
#define HW   1024
#define STEP 20
#define NS   51            // hw // STEP
#define NP   512           // model points
#define NBLK (BS * NS)     // 408 hypotheses
#define NT   256           // threads per block (8 warps)
#define NTILE (NP / 8)     // 64 n-tiles of 8 GT points
#define SW   520           // smem row stride (words): 512 + 8 prefetch pad
#define SCORING_WEIGHT 0.01f

// Dynamic smem: [r_hi 4*SW][r_lo 4*SW][pn_s NP][red NT]  (19712 bytes)
#define SMEM_WORDS (8 * SW + NP + NT)

// Scratch (no allocations allowed)
__device__ float    g_part[NBLK];
__device__ unsigned g_count = 0;   // last-block-done counter; self-resetting

__device__ __forceinline__ unsigned f2tf(float f) {
    unsigned r; asm("cvt.rna.tf32.f32 %0, %1;" : "=r"(r) : "f"(f)); return r;
}

// D = A(tf32 m16k8,row) * B(tf32 k8n8,col) + 0
#define MMA_Z(D0,D1,D2,D3,A0,A1,A2,A3,B0,B1,Z)                                 \
    asm("mma.sync.aligned.m16n8k8.row.col.f32.tf32.tf32.f32 "                  \
        "{%0,%1,%2,%3}, {%4,%5,%6,%7}, {%8,%9}, {%10,%10,%10,%10};"            \
        : "=f"(D0),"=f"(D1),"=f"(D2),"=f"(D3)                                  \
        : "r"(A0),"r"(A1),"r"(A2),"r"(A3), "r"(B0),"r"(B1), "f"(Z))

// ---------------------------------------------------------------------------
// One block per (batch, sample) hypothesis, 8 warps, tensor-core NN:
//   A (m16 x k8) = [-2*pred_hi (k0..2) | 1 | -2*pred_lo (k4..6) | 0]
//   B_hi (k8 x n8) = [gt_hi,gn_hi ; gt_hi,gn_hi]   B_lo = [gt_lo,gn_lo ; 0]
//   e = A*B_hi, f = A*B_lo  (INDEPENDENT HMMAs), d = e+f = gn - 2 p.g
// split-tf32 accuracy (drops lo*lo ~2^-22). Warp w owns m-rows [64w,64w+64)
// (4 m-tiles, A register-resident); per n-tile: 8 indep HMMA + 4 FADD +
// 4 FMNMX, B prefetched one tile ahead. Smem phase-aliased: pred staging ->
// A fragments -> same buffers refilled with GT for the B source.
// ---------------------------------------------------------------------------
__global__ __launch_bounds__(NT, 3) void fused_kernel(
    const float* __restrict__ pred_r,
    const float* __restrict__ pred_t,
    const float* __restrict__ pred_s,
    const float* __restrict__ gt_r,
    const float* __restrict__ gt_t,
    const float* __restrict__ model,
    float* __restrict__ out)
{
    extern __shared__ unsigned dsm[];
    unsigned* r_hi = dsm;                        // 4*SW
    unsigned* r_lo = dsm + 4 * SW;               // 4*SW
    float*    pn_s = (float*)(dsm + 8 * SW);     // NP
    float*    red  = (float*)(dsm + 8 * SW + NP);// NT
    __shared__ bool s_last;

    int blk = blockIdx.x;
    int b   = blk / NS;
    int pix = (blk % NS) * STEP;
    int tid = threadIdx.x;

    const float* m = model + b * 3 * NP;

    // ---- pose (tiny, redundant per thread) ----
    const float* pr = pred_r + b * 4 * HW + pix;
    float q0 = pr[0], q1 = pr[HW], q2 = pr[2 * HW], q3 = pr[3 * HW];
    float inv = rsqrtf(q0 * q0 + q1 * q1 + q2 * q2 + q3 * q3);
    q0 *= inv; q1 *= inv; q2 *= inv; q3 *= inv;

    float R00 = 1.0f - 2.0f * (q2 * q2 + q3 * q3);
    float R01 = 2.0f * (q1 * q2 - q0 * q3);
    float R02 = 2.0f * (q0 * q2 + q1 * q3);
    float R10 = 2.0f * (q1 * q2 + q3 * q0);
    float R11 = 1.0f - 2.0f * (q1 * q1 + q3 * q3);
    float R12 = 2.0f * (q2 * q3 - q0 * q1);
    float R20 = 2.0f * (q1 * q3 - q0 * q2);
    float R21 = 2.0f * (q0 * q1 + q2 * q3);
    float R22 = 1.0f - 2.0f * (q1 * q1 + q2 * q2);

    const float* pt = pred_t + b * 3 * HW + pix;
    float tx = pt[0], ty = pt[HW], tz = pt[2 * HW];

    float mv[2][3];
#pragma unroll
    for (int k = 0; k < 2; k++) {
        int p = tid + k * NT;
        mv[k][0] = m[p]; mv[k][1] = m[NP + p]; mv[k][2] = m[2 * NP + p];
    }

    // ---- phase 1: pred points -> A staging ----
#pragma unroll
    for (int k = 0; k < 2; k++) {
        int p = tid + k * NT;
        float vx = mv[k][0], vy = mv[k][1], vz = mv[k][2];
        float px = fmaf(R00, vx, fmaf(R01, vy, fmaf(R02, vz, tx)));
        float py = fmaf(R10, vx, fmaf(R11, vy, fmaf(R12, vz, ty)));
        float pz = fmaf(R20, vx, fmaf(R21, vy, fmaf(R22, vz, tz)));
        pn_s[p] = fmaf(px, px, fmaf(py, py, pz * pz));
        float av[3] = { -2.0f * px, -2.0f * py, -2.0f * pz };
#pragma unroll
        for (int c = 0; c < 3; c++) {
            unsigned hi = f2tf(av[c]);
            r_hi[c * SW + p] = hi;
            r_lo[c * SW + p] = f2tf(av[c] - __uint_as_float(hi));
        }
        r_hi[3 * SW + p] = f2tf(1.0f);
        r_lo[3 * SW + p] = 0u;
    }
    __syncthreads();

    int lane = tid & 31;
    int w    = tid >> 5;       // warp 0..7
    int lq   = lane >> 2;      // 0..7
    int lk   = lane & 3;       // 0..3
    int mbase = w * 64;

    // ---- phase 2: A fragments (register-resident) ----
    unsigned Ah0[4], Ah1[4], Al0[4], Al1[4];
#pragma unroll
    for (int mt = 0; mt < 4; mt++) {
        int r0 = mbase + mt * 16 + lq;
        Ah0[mt] = r_hi[lk * SW + r0];
        Ah1[mt] = r_hi[lk * SW + r0 + 8];
        Al0[mt] = r_lo[lk * SW + r0];
        Al1[mt] = r_lo[lk * SW + r0 + 8];
    }
    __syncthreads();

    // ---- phase 3: GT points -> B source (reuse the same buffers) ----
    {
        const float* GR = gt_r + b * 9;
        const float* GT = gt_t + b * 3;
        float G0 = GR[0], G1 = GR[1], G2 = GR[2];
        float G3 = GR[3], G4 = GR[4], G5 = GR[5];
        float G6 = GR[6], G7 = GR[7], G8 = GR[8];
        float T0 = GT[0], T1 = GT[1], T2 = GT[2];
#pragma unroll
        for (int k = 0; k < 2; k++) {
            int p = tid + k * NT;
            float vx = mv[k][0], vy = mv[k][1], vz = mv[k][2];
            float gx = fmaf(G0, vx, fmaf(G1, vy, fmaf(G2, vz, T0)));
            float gy = fmaf(G3, vx, fmaf(G4, vy, fmaf(G5, vz, T1)));
            float gz = fmaf(G6, vx, fmaf(G7, vy, fmaf(G8, vz, T2)));
            float gn = fmaf(gx, gx, fmaf(gy, gy, gz * gz));
            float gv[4] = { gx, gy, gz, gn };
#pragma unroll
            for (int c = 0; c < 4; c++) {
                unsigned hi = f2tf(gv[c]);
                r_hi[c * SW + p] = hi;
                r_lo[c * SW + p] = f2tf(gv[c] - __uint_as_float(hi));
            }
        }
    }
    __syncthreads();

    float mn[4][4];
#pragma unroll
    for (int mt = 0; mt < 4; mt++)
#pragma unroll
        for (int j = 0; j < 4; j++) mn[mt][j] = 3.0e38f;

    const unsigned* bhp = r_hi + lk * SW + lq;
    const unsigned* blp = r_lo + lk * SW + lq;
    unsigned bz = 0u;
    float    fz = 0.0f;

    // ---- main loop: 8 independent HMMA + 4 FADD + 4 FMNMX per n-tile ----
    unsigned bh = bhp[0], bl = blp[0];
#pragma unroll 2
    for (int nt = 0; nt < NTILE; nt++) {
        unsigned nbh = bhp[(nt + 1) * 8];   // tail read lands in SW padding
        unsigned nbl = blp[(nt + 1) * 8];
#pragma unroll
        for (int mt = 0; mt < 4; mt++) {
            float e0, e1, e2, e3, f0, f1, f2, f3;
            MMA_Z(e0, e1, e2, e3, Ah0[mt], Ah1[mt], Al0[mt], Al1[mt], bh, bh, fz);
            MMA_Z(f0, f1, f2, f3, Ah0[mt], Ah1[mt], Al0[mt], Al1[mt], bl, bz, fz);
            mn[mt][0] = fminf(mn[mt][0], e0 + f0);
            mn[mt][1] = fminf(mn[mt][1], e1 + f1);
            mn[mt][2] = fminf(mn[mt][2], e2 + f2);
            mn[mt][3] = fminf(mn[mt][3], e3 + f3);
        }
        bh = nbh; bl = nbl;
    }

    // ---- epilogue: quad-min, sqrt, sum ----
    float acc = 0.0f;
#pragma unroll
    for (int mt = 0; mt < 4; mt++) {
        float m0 = fminf(mn[mt][0], mn[mt][1]);   // row mbase+mt*16+lq
        float m1 = fminf(mn[mt][2], mn[mt][3]);   // row +8
#pragma unroll
        for (int off = 1; off <= 2; off <<= 1) {
            m0 = fminf(m0, __shfl_xor_sync(0xFFFFFFFFu, m0, off));
            m1 = fminf(m1, __shfl_xor_sync(0xFFFFFFFFu, m1, off));
        }
        if (lk == 0) {
            int r = mbase + mt * 16 + lq;
            acc += sqrtf(fmaxf(pn_s[r] + m0, 0.0f));
            acc += sqrtf(fmaxf(pn_s[r + 8] + m1, 0.0f));
        }
    }
    red[tid] = acc;          // non-(lk==0) threads contribute 0
    __syncthreads();

#pragma unroll
    for (int s = NT / 2; s >= 32; s >>= 1) {   // fold down to 32 inclusive
        if (tid < s) red[tid] += red[tid + s];
        __syncthreads();
    }
    if (tid < 32) {
        float v = red[tid];
#pragma unroll
        for (int o = 16; o > 0; o >>= 1)
            v += __shfl_down_sync(0xFFFFFFFFu, v, o);
        if (tid == 0) {
            float add = v * (1.0f / NP);
            float sc  = pred_s[b * HW + pix];
            g_part[blk] = (add * sc - SCORING_WEIGHT * logf(sc)) * (1.0f / NBLK);
            __threadfence();
            unsigned old = atomicAdd(&g_count, 1u);
            s_last = (old == NBLK - 1);
        }
    }
    __syncthreads();

    // ---- last CTA: reduce 408 partials + inf/nan guard ----
    if (s_last && tid < 32) {
        __threadfence();
        float v = 0.0f;
        for (int i = tid; i < NBLK; i += 32) v += __ldcg(&g_part[i]);
#pragma unroll
        for (int o = 16; o > 0; o >>= 1)
            v += __shfl_down_sync(0xFFFFFFFFu, v, o);
        if (tid == 0) {
            if (isinf(v) || isnan(v)) v = 0.0f;
            out[0] = v;
            g_count = 0;   // reset for next launch / graph replay
        }
    }
}

// ---------------------------------------------------------------------------
// Inputs (metadata order): pred_r, pred_t, pred_s, mask, gt_r, gt_t,
//                          model_xyz, cls_ids
// ---------------------------------------------------------------------------
extern "C" void kernel_launch(void* const* d_in, const int* in_sizes, int n_in,
                              void* d_out, int out_size)
{
    const float* pred_r = (const float*)d_in[0];
    const float* pred_t = (const float*)d_in[1];
    const float* pred_s = (const float*)d_in[2];
    // d_in[3] = mask (unused)
    const float* gt_r   = (const float*)d_in[4];
    const float* gt_t   = (const float*)d_in[5];
    const float* model  = (const float*)d_in[6];
    // d_in[7] = cls_ids (unused)

    fused_kernel<<<NBLK, NT, SMEM_WORDS * 4>>>(pred_r, pred_t, pred_s,
                                               gt_r, gt_t, model,
                                               (float*)d_out);
}

// round 14
// speedup vs baseline: 1.0789x; 1.0789x over previous
#include <cuda_runtime.h>
#include <math.h>

#define BS   8
#define HW   1024
#define STEP 20
#define NS   51            // hw // STEP
#define NP   512           // model points
#define NBLK (BS * NS)     // 408 hypotheses
#define NT   256           // threads per block (8 warps)
#define NTILE (NP / 8)     // 64 n-tiles of 8 GT points
#define SW   536           // smem row stride (words): 512 + 24 (pad + bank split)
#define SCORING_WEIGHT 0.01f

// Dynamic smem: [r_hi 4*SW][r_lo 4*SW][pn_s NP][red NT]
#define SMEM_WORDS (8 * SW + NP + NT)

// Scratch (no allocations allowed)
__device__ float    g_part[NBLK];
__device__ unsigned g_count = 0;   // last-block-done counter; self-resetting

__device__ __forceinline__ unsigned f2tf(float f) {
    unsigned r; asm("cvt.rna.tf32.f32 %0, %1;" : "=r"(r) : "f"(f)); return r;
}

// D = A(tf32 m16k8,row) * B(tf32 k8n8,col) + 0
#define MMA_Z(D0,D1,D2,D3,A0,A1,A2,A3,B0,B1,Z)                                 \
    asm("mma.sync.aligned.m16n8k8.row.col.f32.tf32.tf32.f32 "                  \
        "{%0,%1,%2,%3}, {%4,%5,%6,%7}, {%8,%9}, {%10,%10,%10,%10};"            \
        : "=f"(D0),"=f"(D1),"=f"(D2),"=f"(D3)                                  \
        : "r"(A0),"r"(A1),"r"(A2),"r"(A3), "r"(B0),"r"(B1), "f"(Z))

// D = A * B + C  (C separate from D: the acc HMMA of the split pair)
#define MMA_C(D0,D1,D2,D3,A0,A1,A2,A3,B0,B1,C0,C1,C2,C3)                       \
    asm("mma.sync.aligned.m16n8k8.row.col.f32.tf32.tf32.f32 "                  \
        "{%0,%1,%2,%3}, {%4,%5,%6,%7}, {%8,%9}, {%10,%11,%12,%13};"            \
        : "=f"(D0),"=f"(D1),"=f"(D2),"=f"(D3)                                  \
        : "r"(A0),"r"(A1),"r"(A2),"r"(A3), "r"(B0),"r"(B1),                    \
          "f"(C0),"f"(C1),"f"(C2),"f"(C3))

// ---------------------------------------------------------------------------
// One block per (batch, sample) hypothesis, 8 warps, tensor-core NN:
//   A (m16 x k8) = [-2*pred_hi (k0..2) | 1 | -2*pred_lo (k4..6) | 0]
//   e = A*B_hi (B_hi = [gt_hi,gn_hi ; gt_hi,gn_hi]), d = A*B_lo + e
//   (B_lo = [gt_lo,gn_lo ; 0])  =>  d = gn - 2 p.g, split-tf32 accuracy.
// SOFTWARE-PIPELINED: iteration nt issues the init HMMAs (e) for tile nt+1
// and the acc HMMAs (d) for tile nt, whose inits are a full iteration old
// (~28 issues) -> HMMA latency hidden. B triple-buffered (loaded at nt+2).
// Mins compressed pairwise (row-wise, associative-exact): 8 mn registers.
// ---------------------------------------------------------------------------
__global__ __launch_bounds__(NT, 3) void fused_kernel(
    const float* __restrict__ pred_r,
    const float* __restrict__ pred_t,
    const float* __restrict__ pred_s,
    const float* __restrict__ gt_r,
    const float* __restrict__ gt_t,
    const float* __restrict__ model,
    float* __restrict__ out)
{
    extern __shared__ unsigned dsm[];
    unsigned* r_hi = dsm;                          // 4*SW
    unsigned* r_lo = dsm + 4 * SW;                 // 4*SW
    float*    pn_s = (float*)(dsm + 8 * SW);       // NP
    float*    red  = (float*)(dsm + 8 * SW + NP);  // NT
    __shared__ bool s_last;

    int blk = blockIdx.x;
    int b   = blk / NS;
    int pix = (blk % NS) * STEP;
    int tid = threadIdx.x;

    const float* m = model + b * 3 * NP;

    // ---- pose (tiny, redundant per thread) ----
    const float* pr = pred_r + b * 4 * HW + pix;
    float q0 = pr[0], q1 = pr[HW], q2 = pr[2 * HW], q3 = pr[3 * HW];
    float inv = rsqrtf(q0 * q0 + q1 * q1 + q2 * q2 + q3 * q3);
    q0 *= inv; q1 *= inv; q2 *= inv; q3 *= inv;

    float R00 = 1.0f - 2.0f * (q2 * q2 + q3 * q3);
    float R01 = 2.0f * (q1 * q2 - q0 * q3);
    float R02 = 2.0f * (q0 * q2 + q1 * q3);
    float R10 = 2.0f * (q1 * q2 + q3 * q0);
    float R11 = 1.0f - 2.0f * (q1 * q1 + q3 * q3);
    float R12 = 2.0f * (q2 * q3 - q0 * q1);
    float R20 = 2.0f * (q1 * q3 - q0 * q2);
    float R21 = 2.0f * (q0 * q1 + q2 * q3);
    float R22 = 1.0f - 2.0f * (q1 * q1 + q2 * q2);

    const float* pt = pred_t + b * 3 * HW + pix;
    float tx = pt[0], ty = pt[HW], tz = pt[2 * HW];

    float mv[2][3];
#pragma unroll
    for (int k = 0; k < 2; k++) {
        int p = tid + k * NT;
        mv[k][0] = m[p]; mv[k][1] = m[NP + p]; mv[k][2] = m[2 * NP + p];
    }

    // ---- phase 1: pred points -> A staging ----
#pragma unroll
    for (int k = 0; k < 2; k++) {
        int p = tid + k * NT;
        float vx = mv[k][0], vy = mv[k][1], vz = mv[k][2];
        float px = fmaf(R00, vx, fmaf(R01, vy, fmaf(R02, vz, tx)));
        float py = fmaf(R10, vx, fmaf(R11, vy, fmaf(R12, vz, ty)));
        float pz = fmaf(R20, vx, fmaf(R21, vy, fmaf(R22, vz, tz)));
        pn_s[p] = fmaf(px, px, fmaf(py, py, pz * pz));
        float av[3] = { -2.0f * px, -2.0f * py, -2.0f * pz };
#pragma unroll
        for (int c = 0; c < 3; c++) {
            unsigned hi = f2tf(av[c]);
            r_hi[c * SW + p] = hi;
            r_lo[c * SW + p] = f2tf(av[c] - __uint_as_float(hi));
        }
        r_hi[3 * SW + p] = f2tf(1.0f);
        r_lo[3 * SW + p] = 0u;
    }
    __syncthreads();

    int lane = tid & 31;
    int w    = tid >> 5;       // warp 0..7
    int lq   = lane >> 2;      // 0..7
    int lk   = lane & 3;       // 0..3
    int mbase = w * 64;

    // ---- phase 2: A fragments (register-resident) ----
    unsigned Ah0[4], Ah1[4], Al0[4], Al1[4];
#pragma unroll
    for (int mt = 0; mt < 4; mt++) {
        int r0 = mbase + mt * 16 + lq;
        Ah0[mt] = r_hi[lk * SW + r0];
        Ah1[mt] = r_hi[lk * SW + r0 + 8];
        Al0[mt] = r_lo[lk * SW + r0];
        Al1[mt] = r_lo[lk * SW + r0 + 8];
    }
    __syncthreads();

    // ---- phase 3: GT points -> B source (reuse the same buffers) ----
    {
        const float* GR = gt_r + b * 9;
        const float* GT = gt_t + b * 3;
        float G0 = GR[0], G1 = GR[1], G2 = GR[2];
        float G3 = GR[3], G4 = GR[4], G5 = GR[5];
        float G6 = GR[6], G7 = GR[7], G8 = GR[8];
        float T0 = GT[0], T1 = GT[1], T2 = GT[2];
#pragma unroll
        for (int k = 0; k < 2; k++) {
            int p = tid + k * NT;
            float vx = mv[k][0], vy = mv[k][1], vz = mv[k][2];
            float gx = fmaf(G0, vx, fmaf(G1, vy, fmaf(G2, vz, T0)));
            float gy = fmaf(G3, vx, fmaf(G4, vy, fmaf(G5, vz, T1)));
            float gz = fmaf(G6, vx, fmaf(G7, vy, fmaf(G8, vz, T2)));
            float gn = fmaf(gx, gx, fmaf(gy, gy, gz * gz));
            float gv[4] = { gx, gy, gz, gn };
#pragma unroll
            for (int c = 0; c < 4; c++) {
                unsigned hi = f2tf(gv[c]);
                r_hi[c * SW + p] = hi;
                r_lo[c * SW + p] = f2tf(gv[c] - __uint_as_float(hi));
            }
        }
    }
    __syncthreads();

    // row-wise min accumulators: mnA = row lq, mnB = row lq+8, per m-tile
    float mnA[4], mnB[4];
#pragma unroll
    for (int mt = 0; mt < 4; mt++) { mnA[mt] = 3.0e38f; mnB[mt] = 3.0e38f; }

    const unsigned* bp = r_hi + lk * SW + lq;   // r_lo at +4*SW words
    unsigned bz = 0u;
    float    fz = 0.0f;

    // ---- pipeline prologue ----
    unsigned bh_u = bp[0];              // B_hi(0) (used by tile-0 inits below)
    unsigned bl_u = bp[4 * SW];         // B_lo(0) (accs of tile 0)
    float e[4][4];
#pragma unroll
    for (int mt = 0; mt < 4; mt++)
        MMA_Z(e[mt][0], e[mt][1], e[mt][2], e[mt][3],
              Ah0[mt], Ah1[mt], Al0[mt], Al1[mt], bh_u, bh_u, fz);
    unsigned bh_n = bp[8];              // B_hi(1)
    unsigned bl_m = bp[4 * SW + 8];     // B_lo(1)

    // ---- main loop: accs+mins for nt, inits for nt+1, load B(nt+2) ----
#pragma unroll 2
    for (int nt = 0; nt < NTILE; nt++) {
        unsigned bh_p = bp[(nt + 2) * 8];            // pad reads for nt>=62
        unsigned bl_p = bp[4 * SW + (nt + 2) * 8];

        float en[4][4];
#pragma unroll
        for (int mt = 0; mt < 4; mt++)
            MMA_Z(en[mt][0], en[mt][1], en[mt][2], en[mt][3],
                  Ah0[mt], Ah1[mt], Al0[mt], Al1[mt], bh_n, bh_n, fz);

#pragma unroll
        for (int mt = 0; mt < 4; mt++) {
            float d0, d1, d2, d3;
            MMA_C(d0, d1, d2, d3,
                  Ah0[mt], Ah1[mt], Al0[mt], Al1[mt], bl_u, bz,
                  e[mt][0], e[mt][1], e[mt][2], e[mt][3]);
            mnA[mt] = fminf(mnA[mt], fminf(d0, d1));   // row lq
            mnB[mt] = fminf(mnB[mt], fminf(d2, d3));   // row lq+8
        }

        // rotate pipeline state (renamed by unroll)
#pragma unroll
        for (int mt = 0; mt < 4; mt++)
#pragma unroll
            for (int j = 0; j < 4; j++) e[mt][j] = en[mt][j];
        bl_u = bl_m; bl_m = bl_p; bh_n = bh_p;
    }

    // ---- epilogue: quad-min over cols (lanes lk), sqrt, sum ----
    float acc = 0.0f;
#pragma unroll
    for (int mt = 0; mt < 4; mt++) {
        float m0 = mnA[mt], m1 = mnB[mt];
#pragma unroll
        for (int off = 1; off <= 2; off <<= 1) {
            m0 = fminf(m0, __shfl_xor_sync(0xFFFFFFFFu, m0, off));
            m1 = fminf(m1, __shfl_xor_sync(0xFFFFFFFFu, m1, off));
        }
        if (lk == 0) {
            int r = mbase + mt * 16 + lq;
            acc += sqrtf(fmaxf(pn_s[r] + m0, 0.0f));
            acc += sqrtf(fmaxf(pn_s[r + 8] + m1, 0.0f));
        }
    }
    red[tid] = acc;          // non-(lk==0) threads contribute 0
    __syncthreads();

#pragma unroll
    for (int s = NT / 2; s >= 32; s >>= 1) {   // fold down to 32 inclusive
        if (tid < s) red[tid] += red[tid + s];
        __syncthreads();
    }
    if (tid < 32) {
        float v = red[tid];
#pragma unroll
        for (int o = 16; o > 0; o >>= 1)
            v += __shfl_down_sync(0xFFFFFFFFu, v, o);
        if (tid == 0) {
            float add = v * (1.0f / NP);
            float sc  = pred_s[b * HW + pix];
            g_part[blk] = (add * sc - SCORING_WEIGHT * logf(sc)) * (1.0f / NBLK);
            __threadfence();
            unsigned old = atomicAdd(&g_count, 1u);
            s_last = (old == NBLK - 1);
        }
    }
    __syncthreads();

    // ---- last CTA: reduce 408 partials + inf/nan guard ----
    if (s_last && tid < 32) {
        __threadfence();
        float v = 0.0f;
        for (int i = tid; i < NBLK; i += 32) v += __ldcg(&g_part[i]);
#pragma unroll
        for (int o = 16; o > 0; o >>= 1)
            v += __shfl_down_sync(0xFFFFFFFFu, v, o);
        if (tid == 0) {
            if (isinf(v) || isnan(v)) v = 0.0f;
            out[0] = v;
            g_count = 0;   // reset for next launch / graph replay
        }
    }
}

// ---------------------------------------------------------------------------
// Inputs (metadata order): pred_r, pred_t, pred_s, mask, gt_r, gt_t,
//                          model_xyz, cls_ids
// ---------------------------------------------------------------------------
extern "C" void kernel_launch(void* const* d_in, const int* in_sizes, int n_in,
                              void* d_out, int out_size)
{
    const float* pred_r = (const float*)d_in[0];
    const float* pred_t = (const float*)d_in[1];
    const float* pred_s = (const float*)d_in[2];
    // d_in[3] = mask (unused)
    const float* gt_r   = (const float*)d_in[4];
    const float* gt_t   = (const float*)d_in[5];
    const float* model  = (const float*)d_in[6];
    // d_in[7] = cls_ids (unused)

    fused_kernel<<<NBLK, NT, SMEM_WORDS * 4>>>(pred_r, pred_t, pred_s,
                                               gt_r, gt_t, model,
                                               (float*)d_out);
}

// round 15
// speedup vs baseline: 1.1604x; 1.0755x over previous
#include <cuda_runtime.h>
#include <math.h>

#define BS   8
#define HW   1024
#define STEP 20
#define NS   51            // hw // STEP
#define NP   512           // model points
#define NBLK (BS * NS)     // 408 hypotheses
#define NT   256           // 8 warps: 0-3 tensor path, 4-7 fp32 path
#define NTILE 64           // n-tiles of 8 GT points (tensor path)
#define SW   536           // tf32 smem row stride (words)
#define SCORING_WEIGHT 0.01f

// smem layout (words): [r_hi 4*SW][r_lo 4*SW][fp32 pack NP*4][pn_s 256][red NT]
#define OFF_RLO (4 * SW)
#define OFF_FP  (8 * SW)
#define OFF_PN  (8 * SW + NP * 4)
#define OFF_RED (8 * SW + NP * 4 + 256)
#define SMEM_WORDS (8 * SW + NP * 4 + 256 + NT)

// Scratch (no allocations allowed)
__device__ float    g_part[NBLK];
__device__ unsigned g_count = 0;   // last-block-done counter; self-resetting

__device__ __forceinline__ unsigned f2tf(float f) {
    unsigned r; asm("cvt.rna.tf32.f32 %0, %1;" : "=r"(r) : "f"(f)); return r;
}

// D = A(tf32 m16k8,row) * B(tf32 k8n8,col) + 0
#define MMA_Z(D0,D1,D2,D3,A0,A1,A2,A3,B0,B1,Z)                                 \
    asm("mma.sync.aligned.m16n8k8.row.col.f32.tf32.tf32.f32 "                  \
        "{%0,%1,%2,%3}, {%4,%5,%6,%7}, {%8,%9}, {%10,%10,%10,%10};"            \
        : "=f"(D0),"=f"(D1),"=f"(D2),"=f"(D3)                                  \
        : "r"(A0),"r"(A1),"r"(A2),"r"(A3), "r"(B0),"r"(B1), "f"(Z))

// D = A * B + C
#define MMA_C(D0,D1,D2,D3,A0,A1,A2,A3,B0,B1,C0,C1,C2,C3)                       \
    asm("mma.sync.aligned.m16n8k8.row.col.f32.tf32.tf32.f32 "                  \
        "{%0,%1,%2,%3}, {%4,%5,%6,%7}, {%8,%9}, {%10,%11,%12,%13};"            \
        : "=f"(D0),"=f"(D1),"=f"(D2),"=f"(D3)                                  \
        : "r"(A0),"r"(A1),"r"(A2),"r"(A3), "r"(B0),"r"(B1),                    \
          "f"(C0),"f"(C1),"f"(C2),"f"(C3))

// fp32 packed pair-eval: v = p.g2 + gn2 for 2 candidates, min into accs.
#define PAIR_EVAL(MN0, MN1, PX, PY, PZ, AX, AY, CX, CY)                        \
    asm("{\n\t"                                                                \
        ".reg .b64 v;\n\t"                                                     \
        ".reg .f32 lo, hi;\n\t"                                                \
        "fma.rn.f32x2 v, %2, %7, %8;\n\t"                                      \
        "fma.rn.f32x2 v, %3, %6, v;\n\t"                                       \
        "fma.rn.f32x2 v, %4, %5, v;\n\t"                                       \
        "mov.b64 {lo, hi}, v;\n\t"                                             \
        "min.f32 %0, %0, lo;\n\t"                                              \
        "min.f32 %1, %1, hi;\n\t"                                              \
        "}"                                                                    \
        : "+f"(MN0), "+f"(MN1)                                                 \
        : "l"(PZ), "l"(PY), "l"(PX), "l"(AX), "l"(AY), "l"(CX), "l"(CY))

// ---------------------------------------------------------------------------
// One block per hypothesis, 8 warps, PIPE-HYBRID:
//   warps 0-3 (one per SMSP): tensor path (split-tf32 HMMA, R14 pipeline)
//     on query rows [0,256) -- uses the tensor pipe.
//   warps 4-7 (one per SMSP): fp32 f32x2 path on query rows [256,512),
//     each thread 2 queries x all 512 candidates -- uses fma/alu pipes.
// The two warp types interleave on each scheduler, filling each other's
// dependency-stall windows. Results merge in the common block reduction.
// ---------------------------------------------------------------------------
__global__ __launch_bounds__(NT, 3) void fused_kernel(
    const float* __restrict__ pred_r,
    const float* __restrict__ pred_t,
    const float* __restrict__ pred_s,
    const float* __restrict__ gt_r,
    const float* __restrict__ gt_t,
    const float* __restrict__ model,
    float* __restrict__ out)
{
    extern __shared__ unsigned dsm[];
    unsigned* r_hi = dsm;                       // tf32 hi (A staging, then B)
    unsigned* r_lo = dsm + OFF_RLO;             // tf32 lo
    float*    fp   = (float*)(dsm + OFF_FP);    // fp32 packed candidate pairs
    float*    pn_s = (float*)(dsm + OFF_PN);    // pn for rows [0,256)
    float*    red  = (float*)(dsm + OFF_RED);   // block reduction
    __shared__ bool s_last;

    int blk = blockIdx.x;
    int b   = blk / NS;
    int pix = (blk % NS) * STEP;
    int tid = threadIdx.x;

    const float* m = model + b * 3 * NP;

    // ---- pose (redundant per thread) ----
    const float* pr = pred_r + b * 4 * HW + pix;
    float q0 = pr[0], q1 = pr[HW], q2 = pr[2 * HW], q3 = pr[3 * HW];
    float inv = rsqrtf(q0 * q0 + q1 * q1 + q2 * q2 + q3 * q3);
    q0 *= inv; q1 *= inv; q2 *= inv; q3 *= inv;

    float R00 = 1.0f - 2.0f * (q2 * q2 + q3 * q3);
    float R01 = 2.0f * (q1 * q2 - q0 * q3);
    float R02 = 2.0f * (q0 * q2 + q1 * q3);
    float R10 = 2.0f * (q1 * q2 + q3 * q0);
    float R11 = 1.0f - 2.0f * (q1 * q1 + q3 * q3);
    float R12 = 2.0f * (q2 * q3 - q0 * q1);
    float R20 = 2.0f * (q1 * q3 - q0 * q2);
    float R21 = 2.0f * (q0 * q1 + q2 * q3);
    float R22 = 1.0f - 2.0f * (q1 * q1 + q2 * q2);

    const float* pt = pred_t + b * 3 * HW + pix;
    float tx = pt[0], ty = pt[HW], tz = pt[2 * HW];

    const float* GR = gt_r + b * 9;
    const float* GTt = gt_t + b * 3;
    float G0 = GR[0], G1 = GR[1], G2 = GR[2];
    float G3 = GR[3], G4 = GR[4], G5 = GR[5];
    float G6 = GR[6], G7 = GR[7], G8 = GR[8];
    float T0 = GTt[0], T1 = GTt[1], T2 = GTt[2];

    // ---- phase 1: GT both formats (kept for phase 3) + A staging row tid ----
    float gv[2][4];
#pragma unroll
    for (int k = 0; k < 2; k++) {
        int p = tid + k * NT;
        float vx = m[p], vy = m[NP + p], vz = m[2 * NP + p];
        float gx = fmaf(G0, vx, fmaf(G1, vy, fmaf(G2, vz, T0)));
        float gy = fmaf(G3, vx, fmaf(G4, vy, fmaf(G5, vz, T1)));
        float gz = fmaf(G6, vx, fmaf(G7, vy, fmaf(G8, vz, T2)));
        float gn = fmaf(gx, gx, fmaf(gy, gy, gz * gz));
        gv[k][0] = gx; gv[k][1] = gy; gv[k][2] = gz; gv[k][3] = gn;
        // fp32 pack: pair layout [x0,x1,y0,y1,z0,z1,w0,w1], (x,y,z) = -2g
        float* dst = fp + 8 * (p >> 1) + (p & 1);
        dst[0] = -2.0f * gx;
        dst[2] = -2.0f * gy;
        dst[4] = -2.0f * gz;
        dst[6] = gn;
        if (k == 0) {   // A staging: pred row p = tid (rows 0..255)
            float px = fmaf(R00, vx, fmaf(R01, vy, fmaf(R02, vz, tx)));
            float py = fmaf(R10, vx, fmaf(R11, vy, fmaf(R12, vz, ty)));
            float pz = fmaf(R20, vx, fmaf(R21, vy, fmaf(R22, vz, tz)));
            pn_s[p] = fmaf(px, px, fmaf(py, py, pz * pz));
            float av[3] = { -2.0f * px, -2.0f * py, -2.0f * pz };
#pragma unroll
            for (int c = 0; c < 3; c++) {
                unsigned hi = f2tf(av[c]);
                r_hi[c * SW + p] = hi;
                r_lo[c * SW + p] = f2tf(av[c] - __uint_as_float(hi));
            }
            r_hi[3 * SW + p] = f2tf(1.0f);
            r_lo[3 * SW + p] = 0u;
        }
    }
    __syncthreads();

    int lane = tid & 31;
    int w    = tid >> 5;

    // ---- phase 2: tensor warps load A fragments ----
    unsigned Ah0[4], Ah1[4], Al0[4], Al1[4];
    int lq = lane >> 2, lk = lane & 3, mbase = w * 64;
    if (w < 4) {
#pragma unroll
        for (int mt = 0; mt < 4; mt++) {
            int r0 = mbase + mt * 16 + lq;
            Ah0[mt] = r_hi[lk * SW + r0];
            Ah1[mt] = r_hi[lk * SW + r0 + 8];
            Al0[mt] = r_lo[lk * SW + r0];
            Al1[mt] = r_lo[lk * SW + r0 + 8];
        }
    }
    __syncthreads();

    // ---- phase 3: B tf32 staging (overwrite A buffers) ----
#pragma unroll
    for (int k = 0; k < 2; k++) {
        int p = tid + k * NT;
#pragma unroll
        for (int c = 0; c < 4; c++) {
            unsigned hi = f2tf(gv[k][c]);
            r_hi[c * SW + p] = hi;
            r_lo[c * SW + p] = f2tf(gv[k][c] - __uint_as_float(hi));
        }
    }
    __syncthreads();

    float acc = 0.0f;

    if (w < 4) {
        // ================= TENSOR PATH: rows [0,256) =================
        float mnA[4], mnB[4];
#pragma unroll
        for (int mt = 0; mt < 4; mt++) { mnA[mt] = 3.0e38f; mnB[mt] = 3.0e38f; }

        const unsigned* bp = r_hi + lk * SW + lq;   // r_lo at +OFF_RLO words
        unsigned bz = 0u;
        float    fz = 0.0f;

        unsigned bh_u = bp[0];
        unsigned bl_u = bp[OFF_RLO];
        float e[4][4];
#pragma unroll
        for (int mt = 0; mt < 4; mt++)
            MMA_Z(e[mt][0], e[mt][1], e[mt][2], e[mt][3],
                  Ah0[mt], Ah1[mt], Al0[mt], Al1[mt], bh_u, bh_u, fz);
        unsigned bh_n = bp[8];
        unsigned bl_m = bp[OFF_RLO + 8];

#pragma unroll 2
        for (int nt = 0; nt < NTILE; nt++) {
            unsigned bh_p = bp[(nt + 2) * 8];          // pad reads at tail
            unsigned bl_p = bp[OFF_RLO + (nt + 2) * 8];

            float en[4][4];
#pragma unroll
            for (int mt = 0; mt < 4; mt++)
                MMA_Z(en[mt][0], en[mt][1], en[mt][2], en[mt][3],
                      Ah0[mt], Ah1[mt], Al0[mt], Al1[mt], bh_n, bh_n, fz);

#pragma unroll
            for (int mt = 0; mt < 4; mt++) {
                float d0, d1, d2, d3;
                MMA_C(d0, d1, d2, d3,
                      Ah0[mt], Ah1[mt], Al0[mt], Al1[mt], bl_u, bz,
                      e[mt][0], e[mt][1], e[mt][2], e[mt][3]);
                mnA[mt] = fminf(mnA[mt], fminf(d0, d1));
                mnB[mt] = fminf(mnB[mt], fminf(d2, d3));
            }
#pragma unroll
            for (int mt = 0; mt < 4; mt++)
#pragma unroll
                for (int j = 0; j < 4; j++) e[mt][j] = en[mt][j];
            bl_u = bl_m; bl_m = bl_p; bh_n = bh_p;
        }

#pragma unroll
        for (int mt = 0; mt < 4; mt++) {
            float m0 = mnA[mt], m1 = mnB[mt];
#pragma unroll
            for (int off = 1; off <= 2; off <<= 1) {
                m0 = fminf(m0, __shfl_xor_sync(0xFFFFFFFFu, m0, off));
                m1 = fminf(m1, __shfl_xor_sync(0xFFFFFFFFu, m1, off));
            }
            if (lk == 0) {
                int r = mbase + mt * 16 + lq;
                acc += sqrtf(fmaxf(pn_s[r] + m0, 0.0f));
                acc += sqrtf(fmaxf(pn_s[r + 8] + m1, 0.0f));
            }
        }
    } else {
        // ================= FP32 PATH: rows [256,512) =================
        int ftid = tid - 128;          // 0..127
        unsigned long long px2[2], py2[2], pz2[2];
        float pn[2];
#pragma unroll
        for (int k = 0; k < 2; k++) {
            int p = 256 + ftid + k * 128;
            float vx = m[p], vy = m[NP + p], vz = m[2 * NP + p];
            float px = fmaf(R00, vx, fmaf(R01, vy, fmaf(R02, vz, tx)));
            float py = fmaf(R10, vx, fmaf(R11, vy, fmaf(R12, vz, ty)));
            float pz = fmaf(R20, vx, fmaf(R21, vy, fmaf(R22, vz, tz)));
            pn[k] = fmaf(px, px, fmaf(py, py, pz * pz));
            unsigned ux = __float_as_uint(px), uy = __float_as_uint(py),
                     uz = __float_as_uint(pz);
            asm("mov.b64 %0, {%1, %1};" : "=l"(px2[k]) : "r"(ux));
            asm("mov.b64 %0, {%1, %1};" : "=l"(py2[k]) : "r"(uy));
            asm("mov.b64 %0, {%1, %1};" : "=l"(pz2[k]) : "r"(uz));
        }

        const ulonglong2* __restrict__ sp = (const ulonglong2*)fp;
        float mn0[2], mn1[2];
        mn0[0] = mn0[1] = mn1[0] = mn1[1] = 3.0e38f;

#pragma unroll 4
        for (int i = 0; i < NP / 2; i++) {      // 256 candidate pairs
            ulonglong2 a = sp[2 * i];           // {x0,x1}, {y0,y1}
            ulonglong2 c = sp[2 * i + 1];       // {z0,z1}, {w0,w1}
            PAIR_EVAL(mn0[0], mn1[0], px2[0], py2[0], pz2[0], a.x, a.y, c.x, c.y);
            PAIR_EVAL(mn0[1], mn1[1], px2[1], py2[1], pz2[1], a.x, a.y, c.x, c.y);
        }
        acc  = sqrtf(fmaxf(pn[0] + fminf(mn0[0], mn1[0]), 0.0f));
        acc += sqrtf(fmaxf(pn[1] + fminf(mn0[1], mn1[1]), 0.0f));
    }

    // ---- common block reduction over all 512 query rows ----
    red[tid] = acc;
    __syncthreads();
#pragma unroll
    for (int s = NT / 2; s >= 32; s >>= 1) {   // fold down to 32 inclusive
        if (tid < s) red[tid] += red[tid + s];
        __syncthreads();
    }
    if (tid < 32) {
        float v = red[tid];
#pragma unroll
        for (int o = 16; o > 0; o >>= 1)
            v += __shfl_down_sync(0xFFFFFFFFu, v, o);
        if (tid == 0) {
            float add = v * (1.0f / NP);
            float sc  = pred_s[b * HW + pix];
            g_part[blk] = (add * sc - SCORING_WEIGHT * logf(sc)) * (1.0f / NBLK);
            __threadfence();
            unsigned old = atomicAdd(&g_count, 1u);
            s_last = (old == NBLK - 1);
        }
    }
    __syncthreads();

    // ---- last CTA: reduce 408 partials + inf/nan guard ----
    if (s_last && tid < 32) {
        __threadfence();
        float v = 0.0f;
        for (int i = tid; i < NBLK; i += 32) v += __ldcg(&g_part[i]);
#pragma unroll
        for (int o = 16; o > 0; o >>= 1)
            v += __shfl_down_sync(0xFFFFFFFFu, v, o);
        if (tid == 0) {
            if (isinf(v) || isnan(v)) v = 0.0f;
            out[0] = v;
            g_count = 0;   // reset for next launch / graph replay
        }
    }
}

// ---------------------------------------------------------------------------
// Inputs (metadata order): pred_r, pred_t, pred_s, mask, gt_r, gt_t,
//                          model_xyz, cls_ids
// ---------------------------------------------------------------------------
extern "C" void kernel_launch(void* const* d_in, const int* in_sizes, int n_in,
                              void* d_out, int out_size)
{
    const float* pred_r = (const float*)d_in[0];
    const float* pred_t = (const float*)d_in[1];
    const float* pred_s = (const float*)d_in[2];
    // d_in[3] = mask (unused)
    const float* gt_r   = (const float*)d_in[4];
    const float* gt_t   = (const float*)d_in[5];
    const float* model  = (const float*)d_in[6];
    // d_in[7] = cls_ids (unused)

    fused_kernel<<<NBLK, NT, SMEM_WORDS * 4>>>(pred_r, pred_t, pred_s,
                                               gt_r, gt_t, model,
                                               (float*)d_out);
}